// round 2
// baseline (speedup 1.0000x reference)
#include <cuda_runtime.h>
#include <math.h>

#define Bz 64
#define Hh 1024
#define NNv 65536
#define Mv 64
#define Rv 4
#define SIMBLK (NNv/64)   /* 1024 sim blocks */
#define CSPBLK 64         /* N/1024 csp blocks per b */
#define ECHUNK 128        /* einsum split-K chunks */
#define EK (NNv/ECHUNK)   /* 512 n per chunk */

// ---------------- scratch (device globals: no allocation allowed) ----------
__device__ float g_E[(size_t)Bz*NNv];            // exp(beta*sim) buffer [B,N]
__device__ float g_wpow_w[(size_t)Bz*NNv];       // write-head w_pow
__device__ float g_wpow_r[(size_t)Rv*Bz*NNv];    // read-head w_pow [R,B,N]
__device__ float g_m1[(size_t)NNv*Mv];           // updated memory
__device__ float g_kn[Bz*Mv];
__device__ float g_ev[Bz*Mv];
__device__ float g_av[Bz*Mv];
__device__ float g_beta[Bz];
__device__ float g_gate[Bz];
__device__ float g_gamma[Bz];
__device__ float g_shift[Bz*3];
__device__ float g_psum[(size_t)Bz*SIMBLK];      // per-block exp partial sums
__device__ float g_sumexp[Bz];
__device__ float g_tpart[Rv*Bz*CSPBLK];          // per-block pow partial sums
__device__ float g_totals[1+Rv];                 // [0]=write total, [1..4]=read totals
__device__ float g_epart[(size_t)Rv*ECHUNK*Bz*Mv]; // einsum split-K partials

__device__ __forceinline__ float clip01(float x){ return fminf(fmaxf(x, 0.f), 1.f); }

// ---------------- kernel 1: head projections (once per step) ---------------
__global__ void heads_kernel(const float* __restrict__ h,
    const float* __restrict__ key_w,   const float* __restrict__ key_b,
    const float* __restrict__ beta_w,  const float* __restrict__ beta_b,
    const float* __restrict__ gate_w,  const float* __restrict__ gate_b,
    const float* __restrict__ shift_w, const float* __restrict__ shift_b,
    const float* __restrict__ gamma_w, const float* __restrict__ gamma_b,
    const float* __restrict__ erase_w, const float* __restrict__ erase_b,
    const float* __restrict__ add_w,   const float* __restrict__ add_b)
{
    __shared__ float hs[Hh];
    __shared__ float ksh[Mv];
    __shared__ float sdot[6];
    __shared__ float sinv;
    const int b = blockIdx.x, t = threadIdx.x;
    for (int i = t; i < Hh; i += 256) hs[i] = h[(size_t)b*Hh + i];
    __syncthreads();

    if (t < 64) {
        float a0=0,a1=0,a2=0,a3=0;
        for (int j = 0; j < Hh; j += 4) {
            a0 = fmaf(hs[j  ], key_w[(j  )*Mv + t], a0);
            a1 = fmaf(hs[j+1], key_w[(j+1)*Mv + t], a1);
            a2 = fmaf(hs[j+2], key_w[(j+2)*Mv + t], a2);
            a3 = fmaf(hs[j+3], key_w[(j+3)*Mv + t], a3);
        }
        ksh[t] = clip01(a0+a1+a2+a3 + key_b[t]);
    } else if (t < 128) {
        const int m = t - 64;
        float a0=0,a1=0,a2=0,a3=0;
        for (int j = 0; j < Hh; j += 4) {
            a0 = fmaf(hs[j  ], erase_w[(j  )*Mv + m], a0);
            a1 = fmaf(hs[j+1], erase_w[(j+1)*Mv + m], a1);
            a2 = fmaf(hs[j+2], erase_w[(j+2)*Mv + m], a2);
            a3 = fmaf(hs[j+3], erase_w[(j+3)*Mv + m], a3);
        }
        g_ev[b*Mv + m] = clip01(a0+a1+a2+a3 + erase_b[m]);
    } else if (t < 192) {
        const int m = t - 128;
        float a0=0,a1=0,a2=0,a3=0;
        for (int j = 0; j < Hh; j += 4) {
            a0 = fmaf(hs[j  ], add_w[(j  )*Mv + m], a0);
            a1 = fmaf(hs[j+1], add_w[(j+1)*Mv + m], a1);
            a2 = fmaf(hs[j+2], add_w[(j+2)*Mv + m], a2);
            a3 = fmaf(hs[j+3], add_w[(j+3)*Mv + m], a3);
        }
        // relu then clip01 == clip01
        g_av[b*Mv + m] = clip01(a0+a1+a2+a3 + add_b[m]);
    } else if (t < 198) {
        const int d = t - 192;
        const float* w; int str, col;
        if      (d == 0) { w = beta_w;  str = 1; col = 0; }
        else if (d == 1) { w = gate_w;  str = 1; col = 0; }
        else if (d == 2) { w = gamma_w; str = 1; col = 0; }
        else             { w = shift_w; str = 3; col = d - 3; }
        float a0=0,a1=0;
        for (int j = 0; j < Hh; j += 2) {
            a0 = fmaf(hs[j  ], w[(j  )*str + col], a0);
            a1 = fmaf(hs[j+1], w[(j+1)*str + col], a1);
        }
        sdot[d] = a0 + a1;
    }
    __syncthreads();

    if (t < 32) {
        float v = ksh[t]*ksh[t] + ksh[t+32]*ksh[t+32];
        #pragma unroll
        for (int off = 16; off; off >>= 1) v += __shfl_xor_sync(0xffffffffu, v, off);
        if (t == 0) sinv = 1.f / (sqrtf(v) + 1e-8f);
    }
    __syncthreads();
    if (t < 64) g_kn[b*Mv + t] = ksh[t] * sinv;
    if (t == 0) {
        g_beta[b]  = fmaxf(sdot[0] + beta_b[0], 0.f);
        g_gate[b]  = clip01(sdot[1] + gate_b[0]);
        g_gamma[b] = 1.f + fmaxf(sdot[2] + gamma_b[0], 0.f);
        float x0 = sdot[3] + shift_b[0];
        float x1 = sdot[4] + shift_b[1];
        float x2 = sdot[5] + shift_b[2];
        float mx = fmaxf(x0, fmaxf(x1, x2));
        float e0 = expf(x0-mx), e1 = expf(x1-mx), e2 = expf(x2-mx);
        float is = 1.f / (e0+e1+e2);
        g_shift[b*3+0] = e0*is; g_shift[b*3+1] = e1*is; g_shift[b*3+2] = e2*is;
    }
}

// ------- kernel 2: E[b,n] = exp(beta[b] * (kn[b]·m[n]) / (||m[n]||+eps)) ---
// sim in [-1,1] (cosine) so exp without max-subtraction is numerically safe
// and mathematically identical to the reference softmax.
__global__ void sim_kernel(const float* __restrict__ mem,
                           const int* __restrict__ bank, int use_m1)
{
    const float* __restrict__ src = use_m1 ? g_m1
                                           : (mem + (size_t)bank[0]*NNv*Mv);
    __shared__ float knT[64*68];   // [k][b], padded
    __shared__ float mt [64*68];   // [k][n], n-tile=64, padded
    __shared__ float invn[64];
    __shared__ float sbeta[64];
    const int t = threadIdx.x;
    const int n0 = blockIdx.x * 64;

    for (int i = t; i < 64*64; i += 256) {
        int bb = i >> 6, mm = i & 63;
        knT[mm*68 + bb] = g_kn[i];
    }
    for (int i = t; i < 64*64; i += 256) {
        int rr = i >> 6, cc = i & 63;
        mt[cc*68 + rr] = src[(size_t)(n0 + rr)*Mv + cc];
    }
    if (t < 64) sbeta[t] = g_beta[t];
    __syncthreads();
    if (t < 64) {
        float s = 0.f;
        #pragma unroll 16
        for (int k = 0; k < 64; k++) { float v = mt[k*68 + t]; s = fmaf(v, v, s); }
        invn[t] = 1.f / (sqrtf(s) + 1e-8f);
    }
    __syncthreads();

    const int by = t >> 5, nx = t & 31;   // 8 b's per thread, 2 n's per thread
    float c[8][2];
    #pragma unroll
    for (int i = 0; i < 8; i++) { c[i][0] = 0.f; c[i][1] = 0.f; }

    #pragma unroll 16
    for (int k = 0; k < 64; k++) {
        const float4 A0 = *(const float4*)&knT[k*68 + 8*by];
        const float4 A1 = *(const float4*)&knT[k*68 + 8*by + 4];
        const float2 Bv = *(const float2*)&mt [k*68 + 2*nx];
        float a[8] = {A0.x, A0.y, A0.z, A0.w, A1.x, A1.y, A1.z, A1.w};
        #pragma unroll
        for (int bi = 0; bi < 8; bi++) {
            c[bi][0] = fmaf(a[bi], Bv.x, c[bi][0]);
            c[bi][1] = fmaf(a[bi], Bv.y, c[bi][1]);
        }
    }

    const float2 iv = *(const float2*)&invn[2*nx];
    float psum[8];
    #pragma unroll
    for (int bi = 0; bi < 8; bi++) {
        const int bb = 8*by + bi;
        const float bt = sbeta[bb];
        float e0 = expf(bt * c[bi][0] * iv.x);
        float e1 = expf(bt * c[bi][1] * iv.y);
        *(float2*)&g_E[(size_t)bb*NNv + n0 + 2*nx] = make_float2(e0, e1);
        psum[bi] = e0 + e1;
    }
    #pragma unroll
    for (int bi = 0; bi < 8; bi++)
        #pragma unroll
        for (int off = 16; off; off >>= 1)
            psum[bi] += __shfl_xor_sync(0xffffffffu, psum[bi], off);
    if (nx == 0) {
        #pragma unroll
        for (int bi = 0; bi < 8; bi++)
            g_psum[(size_t)(8*by + bi)*SIMBLK + blockIdx.x] = psum[bi];
    }
}

// ---------------- deterministic reductions ---------------------------------
__global__ void reduce_sumexp_kernel()
{
    const int b = blockIdx.x, t = threadIdx.x;
    float s = 0.f;
    for (int i = t; i < SIMBLK; i += 256) s += g_psum[(size_t)b*SIMBLK + i];
    __shared__ float red[256];
    red[t] = s; __syncthreads();
    for (int off = 128; off; off >>= 1) { if (t < off) red[t] += red[t+off]; __syncthreads(); }
    if (t == 0) g_sumexp[b] = red[0];
}

__global__ void reduce_total_kernel(int out_off)
{
    const int seg = blockIdx.x, t = threadIdx.x;
    float s = 0.f;
    for (int i = t; i < Bz*CSPBLK; i += 256) s += g_tpart[seg*(Bz*CSPBLK) + i];
    __shared__ float red[256];
    red[t] = s; __syncthreads();
    for (int off = 128; off; off >>= 1) { if (t < off) red[t] += red[t+off]; __syncthreads(); }
    if (t == 0) g_totals[out_off + seg] = red[0];
}

// ----- kernel 3: w_c normalize + gate + 3-tap shift + pow + partial sum ----
__global__ void csp_kernel(const float* __restrict__ wprev_base, int is_read)
{
    const int r  = blockIdx.z;
    const int b  = blockIdx.y;
    const int c0 = blockIdx.x * 1024;
    const size_t head_off = ((size_t)(is_read ? r*Bz : 0) + b) * NNv;
    const float* __restrict__ wp = wprev_base + head_off;
    float* __restrict__ wo = (is_read ? g_wpow_r : g_wpow_w) + head_off;
    const float* __restrict__ Eb = g_E + (size_t)b*NNv;

    __shared__ float wg[1026];
    __shared__ float red[256];
    const float gg   = g_gate[b];
    const float invS = 1.f / g_sumexp[b];
    const float s0 = g_shift[b*3+0], s1 = g_shift[b*3+1], s2 = g_shift[b*3+2];
    const float gm = g_gamma[b];
    const int t = threadIdx.x;

    for (int i = t; i < 1026; i += 256) {
        const int n = c0 + i - 1;
        float v = 0.f;
        if (n >= 0 && n < NNv)
            v = gg * Eb[n] * invS + (1.f - gg) * wp[n];
        wg[i] = v;
    }
    __syncthreads();

    float ls = 0.f;
    #pragma unroll
    for (int j = 0; j < 4; j++) {
        const int i = t + j*256;
        const float wt = fmaf(s0, wg[i], fmaf(s1, wg[i+1], s2*wg[i+2]));
        const float pw = powf(wt, gm);
        wo[c0 + i] = pw;
        ls += pw;
    }
    red[t] = ls; __syncthreads();
    for (int off = 128; off; off >>= 1) { if (t < off) red[t] += red[t+off]; __syncthreads(); }
    if (t == 0)
        g_tpart[(is_read ? r : 0)*(Bz*CSPBLK) + b*CSPBLK + blockIdx.x] = red[0];
}

// --- kernel 4: m1 = m0*(1 - W^T e) + W^T a   (W = wpow_w * inv_total) ------
__global__ void memupdate_kernel(const float* __restrict__ mem,
                                 const int* __restrict__ bank)
{
    const float* __restrict__ m0 = mem + (size_t)bank[0]*NNv*Mv;
    __shared__ float wsh[64*64];   // [k=b][n-local]
    __shared__ float es [64*64];   // [b][m] pre-scaled by inv_total
    __shared__ float as_[64*64];
    const int t = threadIdx.x;
    const int n0 = blockIdx.x * 64;
    const float inv = 1.f / (g_totals[0] + 1e-5f);

    for (int i = t; i < 64*64; i += 256) {
        int bb = i >> 6, nl = i & 63;
        wsh[i] = g_wpow_w[(size_t)bb*NNv + n0 + nl];
    }
    for (int i = t; i < 64*64; i += 256) { es[i] = g_ev[i]*inv; as_[i] = g_av[i]*inv; }
    __syncthreads();

    const int tn = t >> 4, tm = t & 15;   // 4 n x 4 m per thread
    float ce[4][4], ca[4][4];
    #pragma unroll
    for (int i = 0; i < 4; i++)
        #pragma unroll
        for (int j = 0; j < 4; j++) { ce[i][j] = 0.f; ca[i][j] = 0.f; }

    #pragma unroll 16
    for (int k = 0; k < 64; k++) {
        const float4 A  = *(const float4*)&wsh[k*64 + 4*tn];
        const float4 E4 = *(const float4*)&es [k*64 + 4*tm];
        const float4 A4 = *(const float4*)&as_[k*64 + 4*tm];
        float av[4] = {A.x, A.y, A.z, A.w};
        float ev[4] = {E4.x, E4.y, E4.z, E4.w};
        float aa[4] = {A4.x, A4.y, A4.z, A4.w};
        #pragma unroll
        for (int i = 0; i < 4; i++)
            #pragma unroll
            for (int j = 0; j < 4; j++) {
                ce[i][j] = fmaf(av[i], ev[j], ce[i][j]);
                ca[i][j] = fmaf(av[i], aa[j], ca[i][j]);
            }
    }

    #pragma unroll
    for (int i = 0; i < 4; i++) {
        const size_t n = (size_t)(n0 + 4*tn + i);
        const float4 o = *(const float4*)&m0[n*Mv + 4*tm];
        float4 v;
        v.x = o.x*(1.f - ce[i][0]) + ca[i][0];
        v.y = o.y*(1.f - ce[i][1]) + ca[i][1];
        v.z = o.z*(1.f - ce[i][2]) + ca[i][2];
        v.w = o.w*(1.f - ce[i][3]) + ca[i][3];
        *(float4*)&g_m1[n*Mv + 4*tm] = v;
    }
}

// ----- kernel 5: split-K read einsum partials: part[r,c,b,m] ---------------
__global__ void einsum_kernel()
{
    const int chunk = blockIdx.x, r = blockIdx.y;
    const int n0 = chunk * EK;
    __shared__ float ashT[64*68];  // [k][b], padded
    __shared__ float bsh [64*64];  // [k][m]
    const int t = threadIdx.x;
    const int tb = t >> 4, tm = t & 15;  // 4 b x 4 m per thread
    float acc[4][4];
    #pragma unroll
    for (int i = 0; i < 4; i++)
        #pragma unroll
        for (int j = 0; j < 4; j++) acc[i][j] = 0.f;

    for (int sub = 0; sub < EK/64; sub++) {
        const int nb = n0 + sub*64;
        for (int i = t; i < 64*64; i += 256) {
            int bb = i >> 6, kk = i & 63;
            ashT[kk*68 + bb] = g_wpow_r[((size_t)r*Bz + bb)*NNv + nb + kk];
        }
        for (int i = t; i < 64*64; i += 256) {
            int kk = i >> 6, mm = i & 63;
            bsh[i] = g_m1[(size_t)(nb + kk)*Mv + mm];
        }
        __syncthreads();
        #pragma unroll 16
        for (int k = 0; k < 64; k++) {
            const float4 A = *(const float4*)&ashT[k*68 + 4*tb];
            const float4 Bv = *(const float4*)&bsh[k*64 + 4*tm];
            float av[4] = {A.x, A.y, A.z, A.w};
            float bv[4] = {Bv.x, Bv.y, Bv.z, Bv.w};
            #pragma unroll
            for (int i = 0; i < 4; i++)
                #pragma unroll
                for (int j = 0; j < 4; j++)
                    acc[i][j] = fmaf(av[i], bv[j], acc[i][j]);
        }
        __syncthreads();
    }

    const size_t base = ((size_t)r*ECHUNK + chunk) * (Bz*Mv);
    #pragma unroll
    for (int i = 0; i < 4; i++) {
        float4 v = make_float4(acc[i][0], acc[i][1], acc[i][2], acc[i][3]);
        *(float4*)&g_epart[base + (size_t)(4*tb + i)*Mv + 4*tm] = v;
    }
}

// ----- kernel 6: reduce split-K + apply 1/(total_r+eps) + transpose --------
__global__ void reduce_out_kernel(float* __restrict__ out)
{
    const int gid = blockIdx.x*256 + threadIdx.x;   // 0..R*B*M-1
    const int r = gid >> 12;
    const int b = (gid >> 6) & 63;
    const int m = gid & 63;
    const float inv = 1.f / (g_totals[1 + r] + 1e-5f);
    float s = 0.f;
    for (int c = 0; c < ECHUNK; c++)
        s += g_epart[(((size_t)r*ECHUNK + c)*Bz + b)*Mv + m];
    out[(size_t)b*(Rv*Mv) + r*Mv + m] = s * inv;
}

// ---------------------------------------------------------------------------
extern "C" void kernel_launch(void* const* d_in, const int* in_sizes, int n_in,
                              void* d_out, int out_size)
{
    const float* h_t     = (const float*)d_in[0];
    const float* ww      = (const float*)d_in[1];
    const float* wr      = (const float*)d_in[2];
    const float* memory  = (const float*)d_in[3];
    const float* key_w   = (const float*)d_in[4];
    const float* key_b   = (const float*)d_in[5];
    const float* beta_w  = (const float*)d_in[6];
    const float* beta_b  = (const float*)d_in[7];
    const float* gate_w  = (const float*)d_in[8];
    const float* gate_b  = (const float*)d_in[9];
    const float* shift_w = (const float*)d_in[10];
    const float* shift_b = (const float*)d_in[11];
    const float* gamma_w = (const float*)d_in[12];
    const float* gamma_b = (const float*)d_in[13];
    const float* erase_w = (const float*)d_in[14];
    const float* erase_b = (const float*)d_in[15];
    const float* add_w   = (const float*)d_in[16];
    const float* add_b   = (const float*)d_in[17];
    const int*   bank    = (const int*)d_in[18];
    float* out = (float*)d_out;

    // head params (shared by all 5 weight updates)
    heads_kernel<<<Bz, 256>>>(h_t, key_w, key_b, beta_w, beta_b, gate_w, gate_b,
                              shift_w, shift_b, gamma_w, gamma_b,
                              erase_w, erase_b, add_w, add_b);

    // --- write head: content addressing on m0 ---
    sim_kernel<<<SIMBLK, 256>>>(memory, bank, 0);
    reduce_sumexp_kernel<<<Bz, 256>>>();
    csp_kernel<<<dim3(CSPBLK, Bz, 1), 256>>>(ww, 0);
    reduce_total_kernel<<<1, 256>>>(0);

    // --- memory erase/add ---
    memupdate_kernel<<<NNv/64, 256>>>(memory, bank);

    // --- read heads: shared content addressing on m1 ---
    sim_kernel<<<SIMBLK, 256>>>(memory, bank, 1);
    reduce_sumexp_kernel<<<Bz, 256>>>();
    csp_kernel<<<dim3(CSPBLK, Bz, Rv), 256>>>(wr, 1);
    reduce_total_kernel<<<Rv, 256>>>(1);

    // --- read: r[r,b,:] = (wpow_r[r,b,:]/total_r) @ m1 ---
    einsum_kernel<<<dim3(ECHUNK, Rv), 256>>>();
    reduce_out_kernel<<<(Rv*Bz*Mv)/256, 256>>>(out);
}